// round 17
// baseline (speedup 1.0000x reference)
#include <cuda_runtime.h>
#include <cuda_bf16.h>
#include <math.h>
#include <stdint.h>

// Shape: x[2,2048,2048], gate_w[2048,8], gate_b[8], W1[8,2048,5632], b1[8,5632],
//        W2[8,5632,2048], b2[8,2048], out fp32 [2,2048,2048]
#define T_TOK 4096
#define D_DIM 2048
#define F_DIM 5632
#define E_NUM 8
#define N_ASSIGN (T_TOK * 2)
#define MAX_TILES 72

// ---------------- static device scratch ----------------
__device__ int   g_cnt[E_NUM];
__device__ int   g_cur[E_NUM];
__device__ int   g_tok_e[T_TOK][2];
__device__ float g_tok_w[T_TOK][2];
__device__ int   g_tok_pos[T_TOK][2];
__device__ int   g_assign_tok[N_ASSIGN];
__device__ int   g_assign_e[N_ASSIGN];
__device__ float g_assign_w[N_ASSIGN];
__device__ int   g_ntiles;
__device__ int   g_tile_e[MAX_TILES];
__device__ int   g_tile_r0[MAX_TILES];
__device__ int   g_tile_nr[MAX_TILES];
__device__ int   g_fallback;

// bf16 hi/lo split operands (split-bf16 3-MMA scheme)
__device__ __align__(16) __nv_bfloat16 g_xh[(size_t)T_TOK * D_DIM];
__device__ __align__(16) __nv_bfloat16 g_xl[(size_t)T_TOK * D_DIM];
__device__ __align__(16) __nv_bfloat16 g_w1h[(size_t)E_NUM * F_DIM * D_DIM];  // [E][F][D] K-major
__device__ __align__(16) __nv_bfloat16 g_w1l[(size_t)E_NUM * F_DIM * D_DIM];
__device__ __align__(16) __nv_bfloat16 g_w2h[(size_t)E_NUM * D_DIM * F_DIM];  // [E][D][F] K-major
__device__ __align__(16) __nv_bfloat16 g_w2l[(size_t)E_NUM * D_DIM * F_DIM];
__device__ __align__(16) __nv_bfloat16 g_hh[(size_t)N_ASSIGN * F_DIM];        // GELU out hi
__device__ __align__(16) __nv_bfloat16 g_hl[(size_t)N_ASSIGN * F_DIM];        // GELU out lo
__device__ __align__(16) float         g_y[(size_t)N_ASSIGN * D_DIM];

// ---------------- helpers ----------------
__device__ __forceinline__ uint32_t smem_u32(const void* p) {
    uint32_t a;
    asm("{ .reg .u64 t; cvta.to.shared.u64 t, %1; cvt.u32.u64 %0, t; }" : "=r"(a) : "l"(p));
    return a;
}

#define CPA16(dst, src) \
    asm volatile("cp.async.cg.shared.global [%0], [%1], 16;" :: "r"(dst), "l"(src))
#define CPA_COMMIT() asm volatile("cp.async.commit_group;" ::: "memory")
#define CPA_WAIT0()  asm volatile("cp.async.wait_group 0;" ::: "memory")

#define LDSM4(d0, d1, d2, d3, addr) \
    asm volatile("ldmatrix.sync.aligned.m8n8.x4.shared.b16 {%0,%1,%2,%3}, [%4];" \
                 : "=r"(d0), "=r"(d1), "=r"(d2), "=r"(d3) : "r"(addr))

#define MMA16816(c, a, b) \
    asm volatile("mma.sync.aligned.m16n8k16.row.col.f32.bf16.bf16.f32 " \
                 "{%0,%1,%2,%3}, {%4,%5,%6,%7}, {%8,%9}, {%0,%1,%2,%3};" \
                 : "+f"((c)[0]), "+f"((c)[1]), "+f"((c)[2]), "+f"((c)[3]) \
                 : "r"((a)[0]), "r"((a)[1]), "r"((a)[2]), "r"((a)[3]), \
                   "r"((b)[0]), "r"((b)[1]))

// f32x2 packed math (proven in R5)
__device__ __forceinline__ unsigned long long pack2(float lo, float hi) {
    unsigned long long r;
    asm("mov.b64 %0, {%1, %2};" : "=l"(r) : "f"(lo), "f"(hi));
    return r;
}
__device__ __forceinline__ void unpack2(unsigned long long v, float& lo, float& hi) {
    asm("mov.b64 {%0, %1}, %2;" : "=f"(lo), "=f"(hi) : "l"(v));
}
__device__ __forceinline__ void fma2(unsigned long long& d,
                                     unsigned long long a, unsigned long long b) {
    asm("fma.rn.f32x2 %0, %1, %2, %0;" : "+l"(d) : "l"(a), "l"(b));
}

// split fp32 pair -> bf16 hi pair + bf16 lo pair (lo = exact residual, RN)
__device__ __forceinline__ uint32_t cvt2(float hi_el, float lo_el) {
    uint32_t r;
    asm("cvt.rn.bf16x2.f32 %0, %1, %2;" : "=r"(r) : "f"(hi_el), "f"(lo_el));
    return r;
}
__device__ __forceinline__ void split2(float a0, float a1, uint32_t& h, uint32_t& l) {
    h = cvt2(a1, a0);
    float h0 = __uint_as_float(h << 16);
    float h1 = __uint_as_float(h & 0xffff0000u);
    l = cvt2(a1 - h1, a0 - h0);
}
__device__ __forceinline__ float gelu_exact(float v) {
    return 0.5f * v * (1.0f + erff(v * 0.70710678118654752440f));
}

// ---------------- gating ----------------
__global__ void k_init() {
    if (threadIdx.x < E_NUM) g_cnt[threadIdx.x] = 0;
    if (threadIdx.x == 0) g_fallback = 0;
}

__global__ void k_gate(const float* __restrict__ x, const float* __restrict__ gw,
                       const float* __restrict__ gb) {
    int t = blockIdx.x, tid = threadIdx.x;
    const float* xr = x + (size_t)t * D_DIM;
    float part[E_NUM];
#pragma unroll
    for (int e = 0; e < E_NUM; e++) part[e] = 0.0f;
    for (int d = tid; d < D_DIM; d += 128) {
        float xv = xr[d];
        const float4* g4 = (const float4*)(gw + (size_t)d * E_NUM);
        float4 g0 = g4[0], g1 = g4[1];
        part[0] = fmaf(xv, g0.x, part[0]); part[1] = fmaf(xv, g0.y, part[1]);
        part[2] = fmaf(xv, g0.z, part[2]); part[3] = fmaf(xv, g0.w, part[3]);
        part[4] = fmaf(xv, g1.x, part[4]); part[5] = fmaf(xv, g1.y, part[5]);
        part[6] = fmaf(xv, g1.z, part[6]); part[7] = fmaf(xv, g1.w, part[7]);
    }
    __shared__ float red[E_NUM][128];
#pragma unroll
    for (int e = 0; e < E_NUM; e++) red[e][tid] = part[e];
    __syncthreads();
    for (int s = 64; s > 0; s >>= 1) {
        if (tid < s)
#pragma unroll
            for (int e = 0; e < E_NUM; e++) red[e][tid] += red[e][tid + s];
        __syncthreads();
    }
    if (tid == 0) {
        float l[E_NUM];
#pragma unroll
        for (int e = 0; e < E_NUM; e++) l[e] = red[e][0] + gb[e];
        int i0 = 0;
#pragma unroll
        for (int e = 1; e < E_NUM; e++) if (l[e] > l[i0]) i0 = e;
        int i1 = (i0 == 0) ? 1 : 0;
#pragma unroll
        for (int e = 0; e < E_NUM; e++) if (e != i0 && l[e] > l[i1]) i1 = e;
        float m = l[i0], s = 0.0f;
#pragma unroll
        for (int e = 0; e < E_NUM; e++) s += expf(l[e] - m);
        g_tok_e[t][0] = i0; g_tok_e[t][1] = i1;
        g_tok_w[t][0] = 1.0f / s; g_tok_w[t][1] = expf(l[i1] - m) / s;
        atomicAdd(&g_cnt[i0], 1);
        atomicAdd(&g_cnt[i1], 1);
    }
}

__global__ void k_scan() {
    int off[E_NUM + 1];
    off[0] = 0;
    for (int e = 0; e < E_NUM; e++) off[e + 1] = off[e] + g_cnt[e];
    for (int e = 0; e < E_NUM; e++) g_cur[e] = off[e];
    int nt = 0;
    for (int e = 0; e < E_NUM; e++)
        for (int r = off[e]; r < off[e + 1]; r += 128) {
            g_tile_e[nt] = e; g_tile_r0[nt] = r;
            int rem = off[e + 1] - r;
            g_tile_nr[nt] = rem < 128 ? rem : 128;
            nt++;
        }
    g_ntiles = nt;
}

__global__ void k_scatter() {
    int t = blockIdx.x * blockDim.x + threadIdx.x;
    if (t >= T_TOK) return;
#pragma unroll
    for (int k = 0; k < 2; k++) {
        int e = g_tok_e[t][k];
        int pos = atomicAdd(&g_cur[e], 1);
        g_assign_tok[pos] = t;
        g_assign_e[pos] = e;
        g_assign_w[pos] = g_tok_w[t][k];
        g_tok_pos[t][k] = pos;
    }
}

// ---------------- split x -> bf16 hi/lo ----------------
__global__ void k_xsplit(const float* __restrict__ x) {
    int i = blockIdx.x * 256 + threadIdx.x;
    const float4* x4 = (const float4*)x;
    float4 v = x4[i];
    uint32_t h0, l0, h1, l1;
    split2(v.x, v.y, h0, l0);
    split2(v.z, v.w, h1, l1);
    ((uint2*)g_xh)[i] = make_uint2(h0, h1);
    ((uint2*)g_xl)[i] = make_uint2(l0, l1);
}

// ---------------- split + transpose W: [E][K][N] fp32 -> [E][N][K] bf16 hi/lo ----------------
__global__ void k_wsplit(const float* __restrict__ W, __nv_bfloat16* __restrict__ Wh,
                         __nv_bfloat16* __restrict__ Wl, int Kdim, int Ndim, int ntn) {
    __shared__ float s[64][68];
    int e = blockIdx.y;
    int bx = blockIdx.x;
    int ktile = bx / ntn, ntile = bx - ktile * ntn;
    int k0 = ktile * 64, n0 = ntile * 64;
    int tid = threadIdx.x;
    const float* src = W + (size_t)e * Kdim * Ndim;
#pragma unroll
    for (int p = 0; p < 4; p++) {
        int r = p * 16 + (tid >> 4);
        int c4 = (tid & 15) * 4;
        float4 v = *(const float4*)(src + (size_t)(k0 + r) * Ndim + n0 + c4);
        *(float4*)&s[r][c4] = v;
    }
    __syncthreads();
    int n_l = tid & 63;
    int kh = (tid >> 6) * 16;
    uint32_t hh[8], ll[8];
#pragma unroll
    for (int j = 0; j < 8; j++) {
        float a0 = s[kh + 2 * j][n_l];
        float a1 = s[kh + 2 * j + 1][n_l];
        split2(a0, a1, hh[j], ll[j]);
    }
    size_t ob = ((size_t)e * Ndim + n0 + n_l) * (size_t)Kdim + k0 + kh;
    uint4* oh = (uint4*)(Wh + ob);
    uint4* ol = (uint4*)(Wl + ob);
    oh[0] = make_uint4(hh[0], hh[1], hh[2], hh[3]);
    oh[1] = make_uint4(hh[4], hh[5], hh[6], hh[7]);
    ol[0] = make_uint4(ll[0], ll[1], ll[2], ll[3]);
    ol[1] = make_uint4(ll[4], ll[5], ll[6], ll[7]);
}

// ---------------- tensor-core grouped GEMM (identical to R15) ----------------
#define SROW_B   80
#define TILE_B   (128 * SROW_B)
#define SMEM_TOT (4 * TILE_B)

template <int MODE>
__global__ void __launch_bounds__(256) tc_gemm(const float* __restrict__ bias) {
    constexpr int Ktot = (MODE == 0) ? D_DIM : F_DIM;
    constexpr int Ntot = (MODE == 0) ? F_DIM : D_DIM;
    constexpr int KT = Ktot / 32;

    int tile = blockIdx.x;
    if (tile >= g_ntiles) return;
    int e = g_tile_e[tile], row0 = g_tile_r0[tile], nrows = g_tile_nr[tile];
    int n0 = blockIdx.y * 128;
    int tid = threadIdx.x, wid = tid >> 5, lane = tid & 31;

    __shared__ __align__(16) char dsm[SMEM_TOT];
    uint32_t sb32 = smem_u32(dsm);

    int r = tid >> 1;
    int cb = (tid & 1) * 32;
    int rowcA = r < nrows ? r : (nrows - 1);
    const char *srcAH, *srcAL;
    if (MODE == 0) {
        int tok = g_assign_tok[row0 + rowcA];
        srcAH = (const char*)(g_xh + (size_t)tok * D_DIM);
        srcAL = (const char*)(g_xl + (size_t)tok * D_DIM);
    } else {
        srcAH = (const char*)(g_hh + (size_t)(row0 + rowcA) * F_DIM);
        srcAL = (const char*)(g_hl + (size_t)(row0 + rowcA) * F_DIM);
    }
    const __nv_bfloat16* Wh_g = (MODE == 0) ? g_w1h : g_w2h;
    const __nv_bfloat16* Wl_g = (MODE == 0) ? g_w1l : g_w2l;
    const char* srcBH = (const char*)(Wh_g + ((size_t)e * Ntot + n0 + r) * (size_t)Ktot);
    const char* srcBL = (const char*)(Wl_g + ((size_t)e * Ntot + n0 + r) * (size_t)Ktot);
    uint32_t dbase = sb32 + r * SROW_B + cb;

    int wm = (wid & 3) * 32;
    int wn = (wid >> 2) * 64;
    int l8 = lane & 7, g8 = lane >> 3;
    uint32_t aoff[2], boff[4];
#pragma unroll
    for (int mt = 0; mt < 2; mt++)
        aoff[mt] = (uint32_t)((wm + mt * 16 + (g8 & 1) * 8 + l8) * SROW_B + ((g8 >> 1) * 8) * 2);
#pragma unroll
    for (int bt = 0; bt < 4; bt++)
        boff[bt] = (uint32_t)((wn + bt * 16 + (g8 >> 1) * 8 + l8) * SROW_B + ((g8 & 1) * 8) * 2);

    float acc[2][8][4];
#pragma unroll
    for (int mt = 0; mt < 2; mt++)
#pragma unroll
        for (int nt = 0; nt < 8; nt++)
#pragma unroll
            for (int j = 0; j < 4; j++) acc[mt][nt][j] = 0.0f;

    for (int kt = 0; kt < KT; kt++) {
        int ko = kt * 64;
        CPA16(dbase,               srcAH + ko + cb);
        CPA16(dbase + 16,          srcAH + ko + cb + 16);
        CPA16(dbase + TILE_B,      srcAL + ko + cb);
        CPA16(dbase + TILE_B + 16, srcAL + ko + cb + 16);
        CPA16(dbase + 2 * TILE_B,      srcBH + ko + cb);
        CPA16(dbase + 2 * TILE_B + 16, srcBH + ko + cb + 16);
        CPA16(dbase + 3 * TILE_B,      srcBL + ko + cb);
        CPA16(dbase + 3 * TILE_B + 16, srcBL + ko + cb + 16);
        CPA_COMMIT();
        CPA_WAIT0();
        __syncthreads();

#pragma unroll
        for (int ks = 0; ks < 2; ks++) {
            uint32_t kso = ks * 32;
            uint32_t ah[2][4], al[2][4], bh[8][2], bl[8][2];
#pragma unroll
            for (int mt = 0; mt < 2; mt++) {
                LDSM4(ah[mt][0], ah[mt][1], ah[mt][2], ah[mt][3], sb32 + aoff[mt] + kso);
                LDSM4(al[mt][0], al[mt][1], al[mt][2], al[mt][3], sb32 + TILE_B + aoff[mt] + kso);
            }
#pragma unroll
            for (int bt = 0; bt < 4; bt++) {
                LDSM4(bh[2 * bt][0], bh[2 * bt][1], bh[2 * bt + 1][0], bh[2 * bt + 1][1],
                      sb32 + 2 * TILE_B + boff[bt] + kso);
                LDSM4(bl[2 * bt][0], bl[2 * bt][1], bl[2 * bt + 1][0], bl[2 * bt + 1][1],
                      sb32 + 3 * TILE_B + boff[bt] + kso);
            }
#pragma unroll
            for (int mt = 0; mt < 2; mt++)
#pragma unroll
                for (int nt = 0; nt < 8; nt++) {
                    MMA16816(acc[mt][nt], ah[mt], bh[nt]);
                    MMA16816(acc[mt][nt], ah[mt], bl[nt]);
                    MMA16816(acc[mt][nt], al[mt], bh[nt]);
                }
        }
        __syncthreads();
    }

    const float* bp = bias + (size_t)e * Ntot;
#pragma unroll
    for (int mt = 0; mt < 2; mt++) {
        int m_lo = wm + mt * 16 + (lane >> 2);
        int m_hi = m_lo + 8;
#pragma unroll
        for (int nt = 0; nt < 8; nt++) {
            int colg = n0 + wn + nt * 8 + 2 * (lane & 3);
            float b0 = bp[colg], b1 = bp[colg + 1];
            if (MODE == 0) {
                if (m_lo < nrows) {
                    int arow = row0 + m_lo;
                    float f0 = gelu_exact(acc[mt][nt][0] + b0);
                    float f1 = gelu_exact(acc[mt][nt][1] + b1);
                    uint32_t h, l2;
                    split2(f0, f1, h, l2);
                    *(uint32_t*)(g_hh + (size_t)arow * F_DIM + colg) = h;
                    *(uint32_t*)(g_hl + (size_t)arow * F_DIM + colg) = l2;
                }
                if (m_hi < nrows) {
                    int arow = row0 + m_hi;
                    float f0 = gelu_exact(acc[mt][nt][2] + b0);
                    float f1 = gelu_exact(acc[mt][nt][3] + b1);
                    uint32_t h, l2;
                    split2(f0, f1, h, l2);
                    *(uint32_t*)(g_hh + (size_t)arow * F_DIM + colg) = h;
                    *(uint32_t*)(g_hl + (size_t)arow * F_DIM + colg) = l2;
                }
            } else {
                if (m_lo < nrows) {
                    int arow = row0 + m_lo;
                    float w = g_assign_w[arow];
                    float2 v = make_float2((acc[mt][nt][0] + b0) * w, (acc[mt][nt][1] + b1) * w);
                    *(float2*)(g_y + (size_t)arow * D_DIM + colg) = v;
                }
                if (m_hi < nrows) {
                    int arow = row0 + m_hi;
                    float w = g_assign_w[arow];
                    float2 v = make_float2((acc[mt][nt][2] + b0) * w, (acc[mt][nt][3] + b1) * w);
                    *(float2*)(g_y + (size_t)arow * D_DIM + colg) = v;
                }
            }
        }
    }
}

// ---------------- verifier: sample-check tensor output, set fallback flag ----------------
__global__ void k_verify(const float* __restrict__ x,  const float* __restrict__ W1,
                         const float* __restrict__ b1, const float* __restrict__ W2,
                         const float* __restrict__ b2) {
    int tid = threadIdx.x;
    const int rows[4]  = {0, 2731, 5461, N_ASSIGN - 1};
    const int cols1[8] = {1, 701, 1401, 2101, 2801, 3501, 4201, F_DIM - 1};
    const int cols2[4] = {3, 700, 1400, D_DIM - 1};

    if (tid < 32) {                 // GEMM1 samples
        int row = rows[tid >> 3];
        int c   = cols1[tid & 7];
        int tok = g_assign_tok[row];
        int e   = g_assign_e[row];
        float acc = 0.0f;
        const float* xr = x  + (size_t)tok * D_DIM;
        const float* wc = W1 + (size_t)e * D_DIM * F_DIM + c;
        for (int k = 0; k < D_DIM; k++) acc = fmaf(xr[k], wc[(size_t)k * F_DIM], acc);
        float ref = gelu_exact(acc + b1[(size_t)e * F_DIM + c]);
        float got = __bfloat162float(g_hh[(size_t)row * F_DIM + c]) +
                    __bfloat162float(g_hl[(size_t)row * F_DIM + c]);
        if (fabsf(got - ref) > 3e-3f + 3e-3f * fabsf(ref)) g_fallback = 1;
    } else if (tid < 48) {          // GEMM2 samples (uses tensor GEMM1 output as input)
        int s = tid - 32;
        int row = rows[s >> 2];
        int c   = cols2[s & 3];
        int e   = g_assign_e[row];
        float acc = 0.0f;
        const float* wc = W2 + (size_t)e * F_DIM * D_DIM + c;
        for (int k = 0; k < F_DIM; k++) {
            float hv = __bfloat162float(g_hh[(size_t)row * F_DIM + k]) +
                       __bfloat162float(g_hl[(size_t)row * F_DIM + k]);
            acc = fmaf(hv, wc[(size_t)k * D_DIM], acc);
        }
        float ref = (acc + b2[(size_t)e * D_DIM + c]) * g_assign_w[row];
        float got = g_y[(size_t)row * D_DIM + c];
        if (fabsf(got - ref) > 3e-3f + 3e-3f * fabsf(ref)) g_fallback = 1;
    }
}

// ---------------- fallback SIMT f32x2 GEMM (R5-proven core, flag-predicated) ----------------
template <int MODE>
__global__ __launch_bounds__(256, 2) void fb_gemm(const float* __restrict__ Xin,
                                                  const float* __restrict__ Wexp,
                                                  const float* __restrict__ bias) {
    if (!g_fallback) return;
    constexpr int K = (MODE == 0) ? D_DIM : F_DIM;
    constexpr int N = (MODE == 0) ? F_DIM : D_DIM;

    int tile = blockIdx.x;
    if (tile >= g_ntiles) return;
    int e = g_tile_e[tile], row0 = g_tile_r0[tile], nrows = g_tile_nr[tile];
    int n0 = blockIdx.y * 128;

    const float* Bp = Wexp + (size_t)e * K * N;
    __shared__ unsigned long long As2[8][128];
    __shared__ float              Bs[8][128];

    int tid = threadIdx.x;
    int arow_l = tid >> 1;
    int kseg = (tid & 1) * 4;
    int rowc = arow_l < nrows ? arow_l : (nrows - 1);

    size_t aoffel;
    const float* AptrF = 0;
    if (MODE == 0) {
        int token = g_assign_tok[row0 + rowc];
        AptrF = Xin + (size_t)token * D_DIM + kseg;
        aoffel = 0;
    } else {
        aoffel = (size_t)(row0 + rowc) * F_DIM + kseg;
    }
    int bkr = tid >> 5;
    int bc = (tid & 31) * 4;
    const float* Bptr = Bp + (size_t)bkr * N + n0 + bc;

    int ty = tid >> 4, tx = tid & 15;
    int rowb = ty * 8, colb = tx * 8;

    unsigned long long acc[8][4];
#pragma unroll
    for (int rr = 0; rr < 8; rr++)
#pragma unroll
        for (int j = 0; j < 4; j++) acc[rr][j] = 0ull;

    for (int kt = 0; kt < K / 8; kt++) {
        float a0, a1, a2, a3;
        if (MODE == 0) {
            float4 av4 = *(const float4*)(AptrF);
            AptrF += 8;
            a0 = av4.x; a1 = av4.y; a2 = av4.z; a3 = av4.w;
        } else {
            uint2 hx = *(const uint2*)(g_hh + aoffel);
            uint2 lx = *(const uint2*)(g_hl + aoffel);
            aoffel += 8;
            a0 = __bfloat162float(((__nv_bfloat162*)&hx.x)->x) + __bfloat162float(((__nv_bfloat162*)&lx.x)->x);
            a1 = __bfloat162float(((__nv_bfloat162*)&hx.x)->y) + __bfloat162float(((__nv_bfloat162*)&lx.x)->y);
            a2 = __bfloat162float(((__nv_bfloat162*)&hx.y)->x) + __bfloat162float(((__nv_bfloat162*)&lx.y)->x);
            a3 = __bfloat162float(((__nv_bfloat162*)&hx.y)->y) + __bfloat162float(((__nv_bfloat162*)&lx.y)->y);
        }
        float4 bv4 = *(const float4*)(Bptr);
        Bptr += (size_t)8 * N;

        As2[kseg + 0][arow_l] = pack2(a0, a0);
        As2[kseg + 1][arow_l] = pack2(a1, a1);
        As2[kseg + 2][arow_l] = pack2(a2, a2);
        As2[kseg + 3][arow_l] = pack2(a3, a3);
        *(float4*)&Bs[bkr][bc] = bv4;
        __syncthreads();

#pragma unroll
        for (int kk = 0; kk < 8; kk++) {
            ulonglong2 a01 = *(const ulonglong2*)&As2[kk][rowb + 0];
            ulonglong2 a23 = *(const ulonglong2*)&As2[kk][rowb + 2];
            ulonglong2 a45 = *(const ulonglong2*)&As2[kk][rowb + 4];
            ulonglong2 a67 = *(const ulonglong2*)&As2[kk][rowb + 6];
            ulonglong2 b01 = *(const ulonglong2*)&Bs[kk][colb + 0];
            ulonglong2 b23 = *(const ulonglong2*)&Bs[kk][colb + 4];
            unsigned long long av[8] = {a01.x, a01.y, a23.x, a23.y, a45.x, a45.y, a67.x, a67.y};
            unsigned long long bv[4] = {b01.x, b01.y, b23.x, b23.y};
#pragma unroll
            for (int rr = 0; rr < 8; rr++)
#pragma unroll
                for (int j = 0; j < 4; j++) fma2(acc[rr][j], av[rr], bv[j]);
        }
        __syncthreads();
    }

#pragma unroll
    for (int rr = 0; rr < 8; rr++) {
        int lr = rowb + rr;
        if (lr >= nrows) continue;
        int arow = row0 + lr;
        float wrow = (MODE == 1) ? g_assign_w[arow] : 0.0f;
#pragma unroll
        for (int j = 0; j < 4; j++) {
            float lo, hi;
            unpack2(acc[rr][j], lo, hi);
            int c0 = n0 + colb + 2 * j;
            if (MODE == 0) {
                float f0 = gelu_exact(lo + bias[(size_t)e * F_DIM + c0]);
                float f1 = gelu_exact(hi + bias[(size_t)e * F_DIM + c0 + 1]);
                uint32_t h, l2;
                split2(f0, f1, h, l2);
                *(uint32_t*)(g_hh + (size_t)arow * F_DIM + c0) = h;
                *(uint32_t*)(g_hl + (size_t)arow * F_DIM + c0) = l2;
            } else {
                float v0 = (lo + bias[(size_t)e * D_DIM + c0]) * wrow;
                float v1 = (hi + bias[(size_t)e * D_DIM + c0 + 1]) * wrow;
                g_y[(size_t)arow * D_DIM + c0]     = v0;
                g_y[(size_t)arow * D_DIM + c0 + 1] = v1;
            }
        }
    }
}

// ---------------- combine ----------------
__global__ void k_combine(float* __restrict__ out) {
    const int nj = D_DIM / 4;
    int idx = blockIdx.x * blockDim.x + threadIdx.x;
    if (idx >= T_TOK * nj) return;
    int t = idx / nj;
    int j = idx - t * nj;
    int p0 = g_tok_pos[t][0], p1 = g_tok_pos[t][1];
    const float4* y4 = (const float4*)g_y;
    float4 a = y4[(size_t)p0 * nj + j];
    float4 b = y4[(size_t)p1 * nj + j];
    ((float4*)out)[idx] = make_float4(a.x + b.x, a.y + b.y, a.z + b.z, a.w + b.w);
}

// ---------------- launch ----------------
extern "C" void kernel_launch(void* const* d_in, const int* in_sizes, int n_in,
                              void* d_out, int out_size) {
    const float* x  = (const float*)d_in[0];
    const float* gw = (const float*)d_in[1];
    const float* gb = (const float*)d_in[2];
    const float* W1 = (const float*)d_in[3];
    const float* b1 = (const float*)d_in[4];
    const float* W2 = (const float*)d_in[5];
    const float* b2 = (const float*)d_in[6];
    float* out = (float*)d_out;

    k_init<<<1, 32>>>();
    k_gate<<<T_TOK, 128>>>(x, gw, gb);
    k_scan<<<1, 1>>>();
    k_scatter<<<(T_TOK + 255) / 256, 256>>>();

    k_xsplit<<<(T_TOK * D_DIM / 4) / 256, 256>>>(x);
    k_wsplit<<<dim3((D_DIM / 64) * (F_DIM / 64), E_NUM), 256>>>(W1, g_w1h, g_w1l, D_DIM, F_DIM, F_DIM / 64);
    k_wsplit<<<dim3((F_DIM / 64) * (D_DIM / 64), E_NUM), 256>>>(W2, g_w2h, g_w2l, F_DIM, D_DIM, D_DIM / 64);

    tc_gemm<0><<<dim3(MAX_TILES, F_DIM / 128), 256>>>(b1);
    tc_gemm<1><<<dim3(MAX_TILES, D_DIM / 128), 256>>>(b2);

    k_verify<<<1, 64>>>(x, W1, b1, W2, b2);

    fb_gemm<0><<<dim3(MAX_TILES, F_DIM / 128), 256>>>(x, W1, b1);
    fb_gemm<1><<<dim3(MAX_TILES, D_DIM / 128), 256>>>(x, W2, b2);

    k_combine<<<(T_TOK * (D_DIM / 4) + 255) / 256, 256>>>(out);
}